// round 2
// baseline (speedup 1.0000x reference)
#include <cuda_runtime.h>

#define HH 128
#define WW 128
#define CC 392
#define KPOOL 7
#define KK 49
#define MAXN 2048

#define BM 128
#define BN 112
#define BK 8
#define NT 224
#define APAD 8

// Scratch (device globals; no allocation allowed)
__device__ float g_map[HH * WW * CC];            // conv output, [H,W,C]
__device__ float g_off[MAXN * KK * 8];           // per (n,bin): [g][2] offsets in FEATURE coords

// ---------------------------------------------------------------------------
// packed fp32x2 helpers (Blackwell FFMA2 — only reachable via PTX)
// ---------------------------------------------------------------------------
__device__ __forceinline__ unsigned long long pack2(float x, float y) {
    unsigned long long r;
    asm("mov.b64 %0, {%1, %2};" : "=l"(r) : "r"(__float_as_uint(x)), "r"(__float_as_uint(y)));
    return r;
}
__device__ __forceinline__ void ffma2(unsigned long long& d, unsigned long long a, unsigned long long b) {
    asm("fma.rn.f32x2 %0, %1, %2, %0;" : "+l"(d) : "l"(a), "l"(b));
}
__device__ __forceinline__ float2 unpack2(unsigned long long v) {
    unsigned int lo, hi;
    asm("mov.b64 {%0, %1}, %2;" : "=r"(lo), "=r"(hi) : "l"(v));
    float2 r; r.x = __uint_as_float(lo); r.y = __uint_as_float(hi);
    return r;
}

// ---------------------------------------------------------------------------
// 3x3 SAME conv, NHWC fp32. Block: 128 pixels (one full row) x 112 couts.
// 224 threads, 8x8 micro-tile, FFMA2 inner product, double-buffered smem.
// ---------------------------------------------------------------------------
__global__ __launch_bounds__(NT, 2) void conv3x3_kernel(const float* __restrict__ f,
                                                        const float* __restrict__ w)
{
    __shared__ float As[2][BK][BM + APAD];
    __shared__ float Bs[2][BK][BN];

    const int y   = blockIdx.x;
    const int co0 = blockIdx.y * BN;
    const int tid = threadIdx.x;
    const int tm  = tid / 14;          // 0..15
    const int tn  = tid - tm * 14;     // 0..13

    const int bkr = tid / 28;                    // 0..7
    const int bn  = (tid - bkr * 28) * 4;        // 0,4,..,108
    const bool bvalid = (co0 + bn) < CC;         // 392-336=56 (mult of 4) -> whole-float4 guard ok

    unsigned long long acc[8][4];
#pragma unroll
    for (int i = 0; i < 8; ++i)
#pragma unroll
        for (int j = 0; j < 4; ++j) acc[i][j] = 0ULL;

    int tap = 0, ci0 = 0;    // chunk to load
    float4 ra0, ra1, rb;

#define LOAD_CHUNK() do {                                                        \
    int dy_ = tap / 3 - 1, dx_ = tap - (tap / 3) * 3 - 1;                        \
    ra0 = make_float4(0.f, 0.f, 0.f, 0.f); ra1 = ra0; rb = ra0;                  \
    if (tid < BM) {                                                              \
        int yy_ = y + dy_, xx_ = tid + dx_;                                      \
        if ((unsigned)yy_ < HH && (unsigned)xx_ < WW) {                          \
            const float4* p_ = (const float4*)(f + ((size_t)(yy_ * WW + xx_)) * CC + ci0); \
            ra0 = p_[0]; ra1 = p_[1];                                            \
        }                                                                        \
    }                                                                            \
    if (bvalid) {                                                                \
        const float4* p_ = (const float4*)(w + ((size_t)(tap * CC + ci0 + bkr)) * CC + co0 + bn); \
        rb = p_[0];                                                              \
    }                                                                            \
} while (0)

#define STS_CHUNK(B) do {                                                        \
    if (tid < BM) {                                                              \
        As[B][0][tid] = ra0.x; As[B][1][tid] = ra0.y;                            \
        As[B][2][tid] = ra0.z; As[B][3][tid] = ra0.w;                            \
        As[B][4][tid] = ra1.x; As[B][5][tid] = ra1.y;                            \
        As[B][6][tid] = ra1.z; As[B][7][tid] = ra1.w;                            \
    }                                                                            \
    *(float4*)&Bs[B][bkr][bn] = rb;                                              \
} while (0)

    // prologue: chunk 0 -> buffer 0
    LOAD_CHUNK();
    STS_CHUNK(0);
    __syncthreads();

    int buf = 0;
#pragma unroll 1
    for (int c = 0; c < 9 * (CC / BK); ++c) {
        const bool has_next = (c < 9 * (CC / BK) - 1);
        if (has_next) {
            ci0 += BK;
            if (ci0 == CC) { ci0 = 0; ++tap; }
            LOAD_CHUNK();
        }
        // compute on buf
#pragma unroll
        for (int k = 0; k < BK; ++k) {
            float4 a0 = *(const float4*)&As[buf][k][tm * 8];
            float4 a1 = *(const float4*)&As[buf][k][tm * 8 + 4];
            float4 b0 = *(const float4*)&Bs[buf][k][tn * 8];
            float4 b1 = *(const float4*)&Bs[buf][k][tn * 8 + 4];
            unsigned long long bb0 = pack2(b0.x, b0.y);
            unsigned long long bb1 = pack2(b0.z, b0.w);
            unsigned long long bb2 = pack2(b1.x, b1.y);
            unsigned long long bb3 = pack2(b1.z, b1.w);
            float av[8] = {a0.x, a0.y, a0.z, a0.w, a1.x, a1.y, a1.z, a1.w};
#pragma unroll
            for (int i = 0; i < 8; ++i) {
                unsigned long long aa = pack2(av[i], av[i]);
                ffma2(acc[i][0], aa, bb0);
                ffma2(acc[i][1], aa, bb1);
                ffma2(acc[i][2], aa, bb2);
                ffma2(acc[i][3], aa, bb3);
            }
        }
        if (has_next) STS_CHUNK(buf ^ 1);
        __syncthreads();
        buf ^= 1;
    }

    // epilogue: write 8x8 tile
    const int xbase = tm * 8;
    const int nbase = co0 + tn * 8;
#pragma unroll
    for (int i = 0; i < 8; ++i) {
        float* op = g_map + ((size_t)(y * WW + xbase + i)) * CC + nbase;
#pragma unroll
        for (int j = 0; j < 4; ++j) {
            if (nbase + j * 2 < CC) {
                float2 v = unpack2(acc[i][j]);
                *(float2*)(op + j * 2) = v;
            }
        }
    }
#undef LOAD_CHUNK
#undef STS_CHUNK
}

// ---------------------------------------------------------------------------
// Kernel 2: PS-RoI pool of the conv output -> per-bin offsets (feature coords)
// ---------------------------------------------------------------------------
__global__ __launch_bounds__(256) void offset_pool_kernel(const float* __restrict__ rois, int N)
{
    int idx = blockIdx.x * blockDim.x + threadIdx.x;   // (n*49 + bin)
    if (idx >= N * KK) return;
    int n   = idx / KK;
    int bin = idx - n * KK;
    int bi  = bin / KPOOL;   // row i
    int bj  = bin - bi * KPOOL;

    const float* r = rois + n * 5;
    float r1 = r[1], r2 = r[2], r3 = r[3], r4 = r[4];
    float x1 = r1 * 0.0625f;
    float y1 = r2 * 0.0625f;
    float x2 = (r3 + 1.0f) * 0.0625f;
    float y2 = (r4 + 1.0f) * 0.0625f;
    float bw = (x2 - x1) / 7.0f;
    float bh = (y2 - y1) / 7.0f;
    float cx = x1 + ((float)bj + 0.5f) * bw;
    float cy = y1 + ((float)bi + 0.5f) * bh;

    float y0f = floorf(cy), x0f = floorf(cx);
    float wy = cy - y0f,    wx = cx - x0f;
    int iy0 = min(max((int)y0f, 0), HH - 1);
    int iy1 = min(max((int)y0f + 1, 0), HH - 1);
    int ix0 = min(max((int)x0f, 0), WW - 1);
    int ix1 = min(max((int)x0f + 1, 0), WW - 1);

    float w00 = (1.f - wy) * (1.f - wx);
    float w01 = (1.f - wy) * wx;
    float w10 = wy * (1.f - wx);
    float w11 = wy * wx;

    const float* p00 = g_map + ((size_t)(iy0 * WW + ix0)) * CC + bin * 8;
    const float* p01 = g_map + ((size_t)(iy0 * WW + ix1)) * CC + bin * 8;
    const float* p10 = g_map + ((size_t)(iy1 * WW + ix0)) * CC + bin * 8;
    const float* p11 = g_map + ((size_t)(iy1 * WW + ix1)) * CC + bin * 8;

    float rw = r3 - r1 + 1.0f;
    float rh = r4 - r2 + 1.0f;

    float* o = g_off + (size_t)idx * 8;
#pragma unroll
    for (int g = 0; g < 4; ++g) {
        int d0 = g * 2, d1 = g * 2 + 1;
        float px = w00 * p00[d0] + w01 * p01[d0] + w10 * p10[d0] + w11 * p11[d0];
        float py = w00 * p00[d1] + w01 * p01[d1] + w10 * p10[d1] + w11 * p11[d1];
        float ox = (px * rw) * 0.1f * 0.0625f;
        float oy = (py * rh) * 0.1f * 0.0625f;
        o[d0] = ox;
        o[d1] = oy;
    }
}

// ---------------------------------------------------------------------------
// Kernel 3: deformable PS-RoI pool of the raw features -> output [N,8,7,7]
// ---------------------------------------------------------------------------
__global__ __launch_bounds__(256) void deform_pool_kernel(const float* __restrict__ f,
                                                          const float* __restrict__ rois,
                                                          float* __restrict__ out, int N)
{
    int idx = blockIdx.x * blockDim.x + threadIdx.x;   // ((n*49+bin)*8 + d)
    if (idx >= N * KK * 8) return;
    int d   = idx & 7;
    int nb  = idx >> 3;        // n*49+bin
    int n   = nb / KK;
    int bin = nb - n * KK;
    int bi  = bin / KPOOL;
    int bj  = bin - bi * KPOOL;

    const float* r = rois + n * 5;
    float x1 = r[1] * 0.0625f;
    float y1 = r[2] * 0.0625f;
    float x2 = (r[3] + 1.0f) * 0.0625f;
    float y2 = (r[4] + 1.0f) * 0.0625f;
    float bw = (x2 - x1) / 7.0f;
    float bh = (y2 - y1) / 7.0f;
    float cx = x1 + ((float)bj + 0.5f) * bw;
    float cy = y1 + ((float)bi + 0.5f) * bh;

    int g = d >> 1;
    const float* o = g_off + (size_t)nb * 8 + g * 2;
    float sx = cx + o[0];
    float sy = cy + o[1];

    float y0f = floorf(sy), x0f = floorf(sx);
    float wy = sy - y0f,    wx = sx - x0f;
    int iy0 = min(max((int)y0f, 0), HH - 1);
    int iy1 = min(max((int)y0f + 1, 0), HH - 1);
    int ix0 = min(max((int)x0f, 0), WW - 1);
    int ix1 = min(max((int)x0f + 1, 0), WW - 1);

    int ch = bin * 8 + d;
    float v00 = __ldg(f + ((size_t)(iy0 * WW + ix0)) * CC + ch);
    float v01 = __ldg(f + ((size_t)(iy0 * WW + ix1)) * CC + ch);
    float v10 = __ldg(f + ((size_t)(iy1 * WW + ix0)) * CC + ch);
    float v11 = __ldg(f + ((size_t)(iy1 * WW + ix1)) * CC + ch);

    float val = (1.f - wy) * (1.f - wx) * v00 + (1.f - wy) * wx * v01
              + wy * (1.f - wx) * v10 + wy * wx * v11;

    out[((size_t)n * 8 + d) * KK + bin] = val;
}

// ---------------------------------------------------------------------------
extern "C" void kernel_launch(void* const* d_in, const int* in_sizes, int n_in,
                              void* d_out, int out_size)
{
    const float* features = (const float*)d_in[0];  // [1,128,128,392]
    const float* rois     = (const float*)d_in[1];  // [N,5]
    const float* conv_w   = (const float*)d_in[2];  // [3,3,392,392]
    float* out = (float*)d_out;
    int N = in_sizes[1] / 5;

    dim3 gconv(HH, 4);  // 128 rows x 4 cout tiles of 112
    conv3x3_kernel<<<gconv, NT>>>(features, conv_w);

    int t2 = N * KK;
    offset_pool_kernel<<<(t2 + 255) / 256, 256>>>(rois, N);

    int t3 = N * KK * 8;
    deform_pool_kernel<<<(t3 + 255) / 256, 256>>>(features, rois, out, N);
}

// round 6
// speedup vs baseline: 2.1598x; 2.1598x over previous
#include <cuda_runtime.h>
#include <cuda_bf16.h>
#include <cstdint>

#define HH 128
#define WW 128
#define CC 392
#define KPOOL 7
#define KK 49
#define MAXN 2048

#define CPAD 448              // channels padded (14 x 32)
#define PFW 130               // padded spatial (halo 1)
#define KTOT (9 * CPAD)       // 4032
#define NPAD 448
#define NCH 126               // 9 taps * 14 ci-blocks of 32

// smem layout per stage (bytes): A_hi[256*80] A_lo[256*80] B_hi[112*80] B_lo[112*80]
#define ST_AHI 0
#define ST_ALO 20480
#define ST_BHI 40960
#define ST_BLO 49920
#define STAGE_BYTES 58880
#define SMEM_BYTES (2 * STAGE_BYTES)

// ---------------------------------------------------------------------------
// Device scratch (no allocation allowed)
// ---------------------------------------------------------------------------
__device__ __nv_bfloat16 g_pf_hi[PFW * PFW * CPAD];
__device__ __nv_bfloat16 g_pf_lo[PFW * PFW * CPAD];
__device__ __nv_bfloat16 g_wt_hi[NPAD * KTOT];
__device__ __nv_bfloat16 g_wt_lo[NPAD * KTOT];
__device__ float g_map[HH * WW * CC];
__device__ float g_off[MAXN * KK * 8];

// ---------------------------------------------------------------------------
// PTX helpers (all baseline sm_80-era — safe for compute_103)
// ---------------------------------------------------------------------------
__device__ __forceinline__ uint32_t smem_u32(const void* p) {
    uint32_t a;
    asm("{ .reg .u64 t; cvta.to.shared.u64 t, %1; cvt.u32.u64 %0, t; }" : "=r"(a) : "l"(p));
    return a;
}
#define CP16(dst, src) \
    asm volatile("cp.async.cg.shared.global [%0], [%1], 16;" :: "r"(dst), "l"(src))
#define CP_COMMIT() asm volatile("cp.async.commit_group;" ::: "memory")
#define CP_WAIT1() asm volatile("cp.async.wait_group 1;" ::: "memory")
#define CP_WAIT0() asm volatile("cp.async.wait_group 0;" ::: "memory")

#define LDSM4(r, a) \
    asm volatile("ldmatrix.sync.aligned.m8n8.x4.shared.b16 {%0,%1,%2,%3}, [%4];" \
        : "=r"((r)[0]), "=r"((r)[1]), "=r"((r)[2]), "=r"((r)[3]) : "r"(a))
#define LDSM2(r0, r1, a) \
    asm volatile("ldmatrix.sync.aligned.m8n8.x2.shared.b16 {%0,%1}, [%2];" \
        : "=r"(r0), "=r"(r1) : "r"(a))

#define MMA(ar, b0, b1, cc) \
    asm volatile("mma.sync.aligned.m16n8k16.row.col.f32.bf16.bf16.f32 " \
        "{%0,%1,%2,%3}, {%4,%5,%6,%7}, {%8,%9}, {%0,%1,%2,%3};" \
        : "+f"((cc)[0]), "+f"((cc)[1]), "+f"((cc)[2]), "+f"((cc)[3]) \
        : "r"((ar)[0]), "r"((ar)[1]), "r"((ar)[2]), "r"((ar)[3]), "r"(b0), "r"(b1))

#define PASS(A, B) do { \
    MMA((A)[0], (B)[0], (B)[2],  acc[0][0]); MMA((A)[0], (B)[1], (B)[3],  acc[0][1]); \
    MMA((A)[0], (B)[4], (B)[6],  acc[0][2]); MMA((A)[0], (B)[5], (B)[7],  acc[0][3]); \
    MMA((A)[0], (B)[8], (B)[10], acc[0][4]); MMA((A)[0], (B)[9], (B)[11], acc[0][5]); \
    MMA((A)[0], (B)[12], (B)[13], acc[0][6]); \
    MMA((A)[1], (B)[0], (B)[2],  acc[1][0]); MMA((A)[1], (B)[1], (B)[3],  acc[1][1]); \
    MMA((A)[1], (B)[4], (B)[6],  acc[1][2]); MMA((A)[1], (B)[5], (B)[7],  acc[1][3]); \
    MMA((A)[1], (B)[8], (B)[10], acc[1][4]); MMA((A)[1], (B)[9], (B)[11], acc[1][5]); \
    MMA((A)[1], (B)[12], (B)[13], acc[1][6]); \
} while (0)

// ---------------------------------------------------------------------------
// Precompute 1: pad + hi/lo split features -> g_pf_hi/lo [130,130,448]
// ---------------------------------------------------------------------------
__global__ __launch_bounds__(256) void pad_split_features(const float* __restrict__ f)
{
    int idx = blockIdx.x * 256 + threadIdx.x;
    const int TOT = PFW * PFW * (CPAD / 4);
    if (idx >= TOT) return;
    int p = idx / (CPAD / 4);
    int c0 = (idx - p * (CPAD / 4)) * 4;
    int y = p / PFW - 1;
    int x = p - (y + 1) * PFW - 1;
    bool in = ((unsigned)y < HH) && ((unsigned)x < WW);
    uint16_t h[4], l[4];
#pragma unroll
    for (int j = 0; j < 4; ++j) {
        int c = c0 + j;
        float v = (in && c < CC) ? __ldg(f + ((size_t)(y * WW + x)) * CC + c) : 0.f;
        __nv_bfloat16 hb = __float2bfloat16(v);
        float r = v - __bfloat162float(hb);
        __nv_bfloat16 lb = __float2bfloat16(r);
        h[j] = __bfloat16_as_ushort(hb);
        l[j] = __bfloat16_as_ushort(lb);
    }
    size_t o = (size_t)p * CPAD + c0;
    *(uint2*)(g_pf_hi + o) = make_uint2((uint32_t)h[0] | ((uint32_t)h[1] << 16),
                                        (uint32_t)h[2] | ((uint32_t)h[3] << 16));
    *(uint2*)(g_pf_lo + o) = make_uint2((uint32_t)l[0] | ((uint32_t)l[1] << 16),
                                        (uint32_t)l[2] | ((uint32_t)l[3] << 16));
}

// ---------------------------------------------------------------------------
// Precompute 2: transpose + pad + split weights -> g_wt_hi/lo [448][4032]
// w layout: [tap(9)][ci(392)][co(392)] ; k = tap*448 + ci
// ---------------------------------------------------------------------------
__global__ __launch_bounds__(128) void split_weights(const float* __restrict__ w)
{
    int k = blockIdx.x * 128 + threadIdx.x;
    int n = blockIdx.y;
    if (k >= KTOT) return;
    int tap = k / CPAD;
    int ci = k - tap * CPAD;
    float v = 0.f;
    if (ci < CC && n < CC) v = __ldg(w + ((size_t)(tap * CC + ci)) * CC + n);
    __nv_bfloat16 hb = __float2bfloat16(v);
    float r = v - __bfloat162float(hb);
    g_wt_hi[(size_t)n * KTOT + k] = hb;
    g_wt_lo[(size_t)n * KTOT + k] = __float2bfloat16(r);
}

// ---------------------------------------------------------------------------
// Conv as implicit GEMM on mma.sync (HMMA). BM=256 (2 rows), BN=112, BK=32.
// 512 threads, warp grid 8(M)x2(N), warp tile 32x56, 3-pass hi/lo.
// ---------------------------------------------------------------------------
__device__ __forceinline__ void issue_chunk(int c, int s, int tid, int ybase, int n0, uint32_t sm)
{
    int tap = c / 14;
    int ci0 = (c - tap * 14) * 32;
    int dy = tap / 3 - 1;
    int dx = tap - (tap / 3) * 3 - 1;
    uint32_t sbase = sm + s * STAGE_BYTES;
    // A: 256 rows x 64B x 2 mats = 2048 x 16B
#pragma unroll
    for (int t = 0; t < 4; ++t) {
        int i = tid + t * 512;
        int mat = i >> 10;
        int r = (i >> 2) & 255;
        int seg = i & 3;
        const __nv_bfloat16* g = mat ? g_pf_lo : g_pf_hi;
        const __nv_bfloat16* src = g
            + ((size_t)((ybase + (r >> 7) + dy + 1) * PFW + (r & 127) + dx + 1)) * CPAD
            + ci0 + seg * 8;
        uint32_t dst = sbase + mat * 20480 + r * 80 + seg * 16;
        CP16(dst, src);
    }
    // B: 112 rows x 64B x 2 mats = 896 x 16B
#pragma unroll
    for (int t = 0; t < 2; ++t) {
        int i = tid + t * 512;
        if (i < 896) {
            int mat = (i >= 448);
            int ii = i - mat * 448;
            int rr = ii >> 2;
            int seg = ii & 3;
            const __nv_bfloat16* g = mat ? g_wt_lo : g_wt_hi;
            const __nv_bfloat16* src = g + (size_t)(n0 + rr) * KTOT + tap * CPAD + ci0 + seg * 8;
            uint32_t dst = sbase + ST_BHI + mat * 8960 + rr * 80 + seg * 16;
            CP16(dst, src);
        }
    }
    CP_COMMIT();
}

__global__ void __launch_bounds__(512, 1) conv_mma_kernel()
{
    extern __shared__ char smem[];
    uint32_t sm = smem_u32(smem);
    const int tid  = threadIdx.x;
    const int lane = tid & 31;
    const int wid  = tid >> 5;
    const int wm   = wid & 7;
    const int wn   = wid >> 3;
    const int ybase = blockIdx.x * 2;
    const int n0    = blockIdx.y * 112;

    float acc[2][7][4];
#pragma unroll
    for (int i = 0; i < 2; ++i)
#pragma unroll
        for (int j = 0; j < 7; ++j)
#pragma unroll
            for (int q = 0; q < 4; ++q) acc[i][j][q] = 0.f;

    // ldmatrix lane offsets (rows padded to 80B -> conflict-free)
    const uint32_t a_lane  = ((lane & 7) + ((lane >> 3) & 1) * 8) * 80u + (lane >> 4) * 16u;
    const uint32_t b2_lane = (lane & 7) * 80u + ((lane >> 3) & 1) * 16u;
    const uint32_t a_base  = (uint32_t)(wm * 32) * 80u;
    const uint32_t b_base  = (uint32_t)(wn * 56) * 80u;

    issue_chunk(0, 0, tid, ybase, n0, sm);
    issue_chunk(1, 1, tid, ybase, n0, sm);

#pragma unroll 1
    for (int c = 0; c < NCH; ++c) {
        if (c == NCH - 1) { CP_WAIT0(); } else { CP_WAIT1(); }
        __syncthreads();
        const int s = c & 1;
        const uint32_t st  = sm + s * STAGE_BYTES;
        const uint32_t Ahi = st + ST_AHI + a_base;
        const uint32_t Alo = st + ST_ALO + a_base;
        const uint32_t Bhi = st + ST_BHI + b_base;
        const uint32_t Blo = st + ST_BLO + b_base;
#pragma unroll
        for (int ks = 0; ks < 2; ++ks) {
            const uint32_t ko = ks * 32u;
            uint32_t ah[2][4], aw[2][4], bh[14], bl[14];
            LDSM4(ah[0], Ahi + a_lane + ko);
            LDSM4(ah[1], Ahi + 1280u + a_lane + ko);
            LDSM4(&bh[0], Bhi + a_lane + ko);
            LDSM4(&bh[4], Bhi + 1280u + a_lane + ko);
            LDSM4(&bh[8], Bhi + 2560u + a_lane + ko);
            LDSM2(bh[12], bh[13], Bhi + 3840u + b2_lane + ko);
            PASS(ah, bh);                       // hi * hi
            LDSM4(&bl[0], Blo + a_lane + ko);
            LDSM4(&bl[4], Blo + 1280u + a_lane + ko);
            LDSM4(&bl[8], Blo + 2560u + a_lane + ko);
            LDSM2(bl[12], bl[13], Blo + 3840u + b2_lane + ko);
            PASS(ah, bl);                       // hi * lo
            LDSM4(aw[0], Alo + a_lane + ko);
            LDSM4(aw[1], Alo + 1280u + a_lane + ko);
            PASS(aw, bh);                       // lo * hi
        }
        __syncthreads();
        if (c + 2 < NCH) issue_chunk(c + 2, s, tid, ybase, n0, sm);
    }

    // epilogue: write fp32 accumulators to g_map
    const int mbase = blockIdx.x * 256 + wm * 32 + (lane >> 2);
    const int nlane = n0 + wn * 56 + (lane & 3) * 2;
#pragma unroll
    for (int i = 0; i < 2; ++i)
#pragma unroll
        for (int h = 0; h < 2; ++h) {
            const int p = mbase + i * 16 + h * 8;
            float* op = g_map + (size_t)p * CC;
#pragma unroll
            for (int j = 0; j < 7; ++j) {
                int n = nlane + j * 8;
                if (n < CC)
                    *(float2*)(op + n) = make_float2(acc[i][j][h * 2], acc[i][j][h * 2 + 1]);
            }
        }
}

// ---------------------------------------------------------------------------
// Kernel: PS-RoI pool of conv map -> per-bin offsets (feature coords)
// ---------------------------------------------------------------------------
__global__ __launch_bounds__(256) void offset_pool_kernel(const float* __restrict__ rois, int N)
{
    int idx = blockIdx.x * blockDim.x + threadIdx.x;
    if (idx >= N * KK) return;
    int n   = idx / KK;
    int bin = idx - n * KK;
    int bi  = bin / KPOOL;
    int bj  = bin - bi * KPOOL;

    const float* r = rois + n * 5;
    float r1 = r[1], r2 = r[2], r3 = r[3], r4 = r[4];
    float x1 = r1 * 0.0625f;
    float y1 = r2 * 0.0625f;
    float x2 = (r3 + 1.0f) * 0.0625f;
    float y2 = (r4 + 1.0f) * 0.0625f;
    float bw = (x2 - x1) / 7.0f;
    float bh = (y2 - y1) / 7.0f;
    float cx = x1 + ((float)bj + 0.5f) * bw;
    float cy = y1 + ((float)bi + 0.5f) * bh;

    float y0f = floorf(cy), x0f = floorf(cx);
    float wy = cy - y0f,    wx = cx - x0f;
    int iy0 = min(max((int)y0f, 0), HH - 1);
    int iy1 = min(max((int)y0f + 1, 0), HH - 1);
    int ix0 = min(max((int)x0f, 0), WW - 1);
    int ix1 = min(max((int)x0f + 1, 0), WW - 1);

    float w00 = (1.f - wy) * (1.f - wx);
    float w01 = (1.f - wy) * wx;
    float w10 = wy * (1.f - wx);
    float w11 = wy * wx;

    const float* p00 = g_map + ((size_t)(iy0 * WW + ix0)) * CC + bin * 8;
    const float* p01 = g_map + ((size_t)(iy0 * WW + ix1)) * CC + bin * 8;
    const float* p10 = g_map + ((size_t)(iy1 * WW + ix0)) * CC + bin * 8;
    const float* p11 = g_map + ((size_t)(iy1 * WW + ix1)) * CC + bin * 8;

    float rw = r3 - r1 + 1.0f;
    float rh = r4 - r2 + 1.0f;

    float* o = g_off + (size_t)idx * 8;
#pragma unroll
    for (int g = 0; g < 4; ++g) {
        int d0 = g * 2, d1 = g * 2 + 1;
        float px = w00 * p00[d0] + w01 * p01[d0] + w10 * p10[d0] + w11 * p11[d0];
        float py = w00 * p00[d1] + w01 * p01[d1] + w10 * p10[d1] + w11 * p11[d1];
        o[d0] = (px * rw) * 0.1f * 0.0625f;
        o[d1] = (py * rh) * 0.1f * 0.0625f;
    }
}

// ---------------------------------------------------------------------------
// Kernel: deformable PS-RoI pool of raw features -> output [N,8,7,7]
// ---------------------------------------------------------------------------
__global__ __launch_bounds__(256) void deform_pool_kernel(const float* __restrict__ f,
                                                          const float* __restrict__ rois,
                                                          float* __restrict__ out, int N)
{
    int idx = blockIdx.x * blockDim.x + threadIdx.x;
    if (idx >= N * KK * 8) return;
    int d   = idx & 7;
    int nb  = idx >> 3;
    int n   = nb / KK;
    int bin = nb - n * KK;
    int bi  = bin / KPOOL;
    int bj  = bin - bi * KPOOL;

    const float* r = rois + n * 5;
    float x1 = r[1] * 0.0625f;
    float y1 = r[2] * 0.0625f;
    float x2 = (r[3] + 1.0f) * 0.0625f;
    float y2 = (r[4] + 1.0f) * 0.0625f;
    float bw = (x2 - x1) / 7.0f;
    float bh = (y2 - y1) / 7.0f;
    float cx = x1 + ((float)bj + 0.5f) * bw;
    float cy = y1 + ((float)bi + 0.5f) * bh;

    int g = d >> 1;
    const float* o = g_off + (size_t)nb * 8 + g * 2;
    float sx = cx + o[0];
    float sy = cy + o[1];

    float y0f = floorf(sy), x0f = floorf(sx);
    float wy = sy - y0f,    wx = sx - x0f;
    int iy0 = min(max((int)y0f, 0), HH - 1);
    int iy1 = min(max((int)y0f + 1, 0), HH - 1);
    int ix0 = min(max((int)x0f, 0), WW - 1);
    int ix1 = min(max((int)x0f + 1, 0), WW - 1);

    int ch = bin * 8 + d;
    float v00 = __ldg(f + ((size_t)(iy0 * WW + ix0)) * CC + ch);
    float v01 = __ldg(f + ((size_t)(iy0 * WW + ix1)) * CC + ch);
    float v10 = __ldg(f + ((size_t)(iy1 * WW + ix0)) * CC + ch);
    float v11 = __ldg(f + ((size_t)(iy1 * WW + ix1)) * CC + ch);

    float val = (1.f - wy) * (1.f - wx) * v00 + (1.f - wy) * wx * v01
              + wy * (1.f - wx) * v10 + wy * wx * v11;

    out[((size_t)n * 8 + d) * KK + bin] = val;
}

// ---------------------------------------------------------------------------
extern "C" void kernel_launch(void* const* d_in, const int* in_sizes, int n_in,
                              void* d_out, int out_size)
{
    const float* features = (const float*)d_in[0];  // [1,128,128,392]
    const float* rois     = (const float*)d_in[1];  // [N,5]
    const float* conv_w   = (const float*)d_in[2];  // [3,3,392,392]
    float* out = (float*)d_out;
    int N = in_sizes[1] / 5;

    cudaFuncSetAttribute(conv_mma_kernel, cudaFuncAttributeMaxDynamicSharedMemorySize, SMEM_BYTES);

    {
        int tot = PFW * PFW * (CPAD / 4);
        pad_split_features<<<(tot + 255) / 256, 256>>>(features);
        dim3 gw((KTOT + 127) / 128, NPAD);
        split_weights<<<gw, 128>>>(conv_w);
    }

    {
        dim3 g(HH / 2, 4);   // 64 M-tiles (256 pixels each) x 4 N-tiles (112)
        conv_mma_kernel<<<g, 512, SMEM_BYTES>>>();
    }

    int t2 = N * KK;
    offset_pool_kernel<<<(t2 + 255) / 256, 256>>>(rois, N);

    int t3 = N * KK * 8;
    deform_pool_kernel<<<(t3 + 255) / 256, 256>>>(features, rois, out, N);
}

// round 7
// speedup vs baseline: 2.2980x; 1.0640x over previous
#include <cuda_runtime.h>
#include <cuda_bf16.h>
#include <cstdint>

#define HH 128
#define WW 128
#define CC 392
#define KPOOL 7
#define KK 49
#define MAXN 2048

#define CPAD 416              // channels padded (13 x 32)
#define PFW 130               // padded spatial (halo 1)
#define KTOT (9 * CPAD)       // 3744
#define NCH 117               // 9 taps * 13 ci-blocks of 32

// smem per stage (bytes): A_hi[256*80] A_lo[256*80] B_hi[112*80] B_lo[112*80]
#define ST_AHI 0
#define ST_ALO 20480
#define ST_BHI 40960
#define ST_BLO 49920
#define STAGE_BYTES 58880
#define SMEM_BYTES (3 * STAGE_BYTES)

// ---------------------------------------------------------------------------
// Device scratch (no allocation allowed)
// ---------------------------------------------------------------------------
__device__ __nv_bfloat16 g_pf_hi[PFW * PFW * CPAD];
__device__ __nv_bfloat16 g_pf_lo[PFW * PFW * CPAD];
__device__ __nv_bfloat16 g_wt_hi[CC * KTOT];      // [n][k], n = 0..391
__device__ __nv_bfloat16 g_wt_lo[CC * KTOT];
__device__ float g_map[HH * WW * CC];
__device__ float g_off[MAXN * KK * 8];

// ---------------------------------------------------------------------------
// PTX helpers (baseline sm_80-era — safe for compute_103)
// ---------------------------------------------------------------------------
__device__ __forceinline__ uint32_t smem_u32(const void* p) {
    uint32_t a;
    asm("{ .reg .u64 t; cvta.to.shared.u64 t, %1; cvt.u32.u64 %0, t; }" : "=r"(a) : "l"(p));
    return a;
}
#define CP16(dst, src) \
    asm volatile("cp.async.cg.shared.global [%0], [%1], 16;" :: "r"(dst), "l"(src))
#define CP_COMMIT() asm volatile("cp.async.commit_group;" ::: "memory")
#define CP_WAIT2() asm volatile("cp.async.wait_group 2;" ::: "memory")
#define CP_WAIT1() asm volatile("cp.async.wait_group 1;" ::: "memory")
#define CP_WAIT0() asm volatile("cp.async.wait_group 0;" ::: "memory")

#define LDSM4(r, a) \
    asm volatile("ldmatrix.sync.aligned.m8n8.x4.shared.b16 {%0,%1,%2,%3}, [%4];" \
        : "=r"((r)[0]), "=r"((r)[1]), "=r"((r)[2]), "=r"((r)[3]) : "r"(a))
#define LDSM2(r0, r1, a) \
    asm volatile("ldmatrix.sync.aligned.m8n8.x2.shared.b16 {%0,%1}, [%2];" \
        : "=r"(r0), "=r"(r1) : "r"(a))

#define MMA(ar, b0, b1, cc) \
    asm volatile("mma.sync.aligned.m16n8k16.row.col.f32.bf16.bf16.f32 " \
        "{%0,%1,%2,%3}, {%4,%5,%6,%7}, {%8,%9}, {%0,%1,%2,%3};" \
        : "+f"((cc)[0]), "+f"((cc)[1]), "+f"((cc)[2]), "+f"((cc)[3]) \
        : "r"((ar)[0]), "r"((ar)[1]), "r"((ar)[2]), "r"((ar)[3]), "r"(b0), "r"(b1))

#define PASS(A, B) do { \
    MMA((A)[0], (B)[0], (B)[2],  acc[0][0]); MMA((A)[0], (B)[1], (B)[3],  acc[0][1]); \
    MMA((A)[0], (B)[4], (B)[6],  acc[0][2]); MMA((A)[0], (B)[5], (B)[7],  acc[0][3]); \
    MMA((A)[0], (B)[8], (B)[10], acc[0][4]); MMA((A)[0], (B)[9], (B)[11], acc[0][5]); \
    MMA((A)[0], (B)[12], (B)[13], acc[0][6]); \
    MMA((A)[1], (B)[0], (B)[2],  acc[1][0]); MMA((A)[1], (B)[1], (B)[3],  acc[1][1]); \
    MMA((A)[1], (B)[4], (B)[6],  acc[1][2]); MMA((A)[1], (B)[5], (B)[7],  acc[1][3]); \
    MMA((A)[1], (B)[8], (B)[10], acc[1][4]); MMA((A)[1], (B)[9], (B)[11], acc[1][5]); \
    MMA((A)[1], (B)[12], (B)[13], acc[1][6]); \
} while (0)

// ---------------------------------------------------------------------------
// Precompute 1: pad + hi/lo split features -> g_pf_hi/lo [130,130,416]
// ---------------------------------------------------------------------------
__global__ __launch_bounds__(256) void pad_split_features(const float* __restrict__ f)
{
    int idx = blockIdx.x * 256 + threadIdx.x;
    const int TOT = PFW * PFW * (CPAD / 4);
    if (idx >= TOT) return;
    int p = idx / (CPAD / 4);
    int c0 = (idx - p * (CPAD / 4)) * 4;
    int y = p / PFW - 1;
    int x = p - (y + 1) * PFW - 1;
    bool in = ((unsigned)y < HH) && ((unsigned)x < WW);
    uint16_t h[4], l[4];
#pragma unroll
    for (int j = 0; j < 4; ++j) {
        int c = c0 + j;
        float v = (in && c < CC) ? __ldg(f + ((size_t)(y * WW + x)) * CC + c) : 0.f;
        __nv_bfloat16 hb = __float2bfloat16(v);
        float r = v - __bfloat162float(hb);
        __nv_bfloat16 lb = __float2bfloat16(r);
        h[j] = __bfloat16_as_ushort(hb);
        l[j] = __bfloat16_as_ushort(lb);
    }
    size_t o = (size_t)p * CPAD + c0;
    *(uint2*)(g_pf_hi + o) = make_uint2((uint32_t)h[0] | ((uint32_t)h[1] << 16),
                                        (uint32_t)h[2] | ((uint32_t)h[3] << 16));
    *(uint2*)(g_pf_lo + o) = make_uint2((uint32_t)l[0] | ((uint32_t)l[1] << 16),
                                        (uint32_t)l[2] | ((uint32_t)l[3] << 16));
}

// ---------------------------------------------------------------------------
// Precompute 2: coalesced transpose + split weights -> g_wt_hi/lo [392][3744]
// w: [tap(9)][ci(392)][co(392)]; k = tap*416 + ci. 32x32 smem tile transpose.
// grid: (13 ci-tiles, 13 n-tiles, 9 taps), 256 threads (32x8)
// ---------------------------------------------------------------------------
__global__ __launch_bounds__(256) void split_weights(const float* __restrict__ w)
{
    __shared__ float tile[32][33];
    const int tap = blockIdx.z;
    const int ci0 = blockIdx.x * 32;
    const int n0  = blockIdx.y * 32;
    const int tx = threadIdx.x & 31;
    const int ty = threadIdx.x >> 5;
    // read coalesced: rows = ci, cols = n
#pragma unroll
    for (int r = 0; r < 4; ++r) {
        int ci = ci0 + ty + r * 8;
        int n  = n0 + tx;
        float v = 0.f;
        if (ci < CC && n < CC) v = __ldg(w + ((size_t)(tap * CC + ci)) * CC + n);
        tile[ty + r * 8][tx] = v;
    }
    __syncthreads();
    // write coalesced: rows = n, cols = k (ci)
#pragma unroll
    for (int r = 0; r < 4; ++r) {
        int n  = n0 + ty + r * 8;
        int ci = ci0 + tx;
        if (n < CC && ci < CPAD) {
            float v = (ci < CC) ? tile[tx][ty + r * 8] : 0.f;
            __nv_bfloat16 hb = __float2bfloat16(v);
            float res = v - __bfloat162float(hb);
            size_t o = (size_t)n * KTOT + tap * CPAD + ci;
            g_wt_hi[o] = hb;
            g_wt_lo[o] = __float2bfloat16(res);
        }
    }
}

// zero pad columns ci in [392,416) of g_wt (written only when ci tile covers 384..415)
__global__ __launch_bounds__(256) void pad_weights_tail()
{
    // k positions tap*416 + ci for ci in [392,416): 9*24*392 rows... do flat
    int idx = blockIdx.x * 256 + threadIdx.x;
    const int TOT = CC * 9 * (CPAD - CC);   // 392*9*24
    if (idx >= TOT) return;
    int n = idx / (9 * (CPAD - CC));
    int rem = idx - n * 9 * (CPAD - CC);
    int tap = rem / (CPAD - CC);
    int ci = CC + rem - tap * (CPAD - CC);
    size_t o = (size_t)n * KTOT + tap * CPAD + ci;
    g_wt_hi[o] = __float2bfloat16(0.f);
    g_wt_lo[o] = __float2bfloat16(0.f);
}

// ---------------------------------------------------------------------------
// Conv as implicit GEMM on mma.sync. BM=256 (2 rows), BN=112 (or 56 tail),
// BK=32, 512 threads, warp grid 8(M)x2(N), warp tile 32x56, 3-pass hi/lo,
// 3-stage cp.async pipeline.
// ---------------------------------------------------------------------------
__device__ __forceinline__ void issue_chunk(int c, int s, int tid, int ybase,
                                            int n0, int brows, uint32_t sm)
{
    int tap = c / 13;
    int ci0 = (c - tap * 13) * 32;
    int dy = tap / 3 - 1;
    int dx = tap - (tap / 3) * 3 - 1;
    uint32_t sbase = sm + s * STAGE_BYTES;
    // A: 256 rows x 64B x 2 mats = 2048 x 16B over 512 threads
#pragma unroll
    for (int t = 0; t < 4; ++t) {
        int i = tid + t * 512;
        int mat = i >> 10;
        int r = (i >> 2) & 255;
        int seg = i & 3;
        const __nv_bfloat16* g = mat ? g_pf_lo : g_pf_hi;
        const __nv_bfloat16* src = g
            + ((size_t)((ybase + (r >> 7) + dy + 1) * PFW + (r & 127) + dx + 1)) * CPAD
            + ci0 + seg * 8;
        uint32_t dst = sbase + mat * 20480 + r * 80 + seg * 16;
        CP16(dst, src);
    }
    // B: brows rows x 64B x 2 mats = brows*8 x 16B
    const int bops = brows * 8;
#pragma unroll
    for (int t = 0; t < 2; ++t) {
        int i = tid + t * 512;
        if (i < bops) {
            int mat = (i >= brows * 4);
            int ii = i - mat * brows * 4;
            int rr = ii >> 2;
            int seg = ii & 3;
            const __nv_bfloat16* g = mat ? g_wt_lo : g_wt_hi;
            const __nv_bfloat16* src = g + (size_t)(n0 + rr) * KTOT + tap * CPAD + ci0 + seg * 8;
            uint32_t dst = sbase + ST_BHI + mat * 8960 + rr * 80 + seg * 16;
            CP16(dst, src);
        }
    }
    CP_COMMIT();
}

__global__ void __launch_bounds__(512, 1) conv_mma_kernel()
{
    extern __shared__ char smem[];
    uint32_t sm = smem_u32(smem);
    const int tid  = threadIdx.x;
    const int lane = tid & 31;
    const int wid  = tid >> 5;
    const int wm   = wid & 7;
    const int wn   = wid >> 3;
    const int ybase = blockIdx.x * 2;
    const bool tail = (blockIdx.y == 3);
    const int n0    = blockIdx.y * 112;
    const int brows = tail ? 56 : 112;
    const bool active = !tail || (wn == 0);

    float acc[2][7][4];
#pragma unroll
    for (int i = 0; i < 2; ++i)
#pragma unroll
        for (int j = 0; j < 7; ++j)
#pragma unroll
            for (int q = 0; q < 4; ++q) acc[i][j][q] = 0.f;

    const uint32_t a_lane  = ((lane & 7) + ((lane >> 3) & 1) * 8) * 80u + (lane >> 4) * 16u;
    const uint32_t b2_lane = (lane & 7) * 80u + ((lane >> 3) & 1) * 16u;
    const uint32_t a_base  = (uint32_t)(wm * 32) * 80u;
    const uint32_t b_base  = (uint32_t)(wn * 56) * 80u;

    issue_chunk(0, 0, tid, ybase, n0, brows, sm);
    issue_chunk(1, 1, tid, ybase, n0, brows, sm);
    issue_chunk(2, 2, tid, ybase, n0, brows, sm);

    int s = 0;
#pragma unroll 1
    for (int c = 0; c < NCH; ++c) {
        if (c < NCH - 2)      { CP_WAIT2(); }
        else if (c == NCH - 2) { CP_WAIT1(); }
        else                  { CP_WAIT0(); }
        __syncthreads();
        if (active) {
            const uint32_t st  = sm + s * STAGE_BYTES;
            const uint32_t Ahi = st + ST_AHI + a_base;
            const uint32_t Alo = st + ST_ALO + a_base;
            const uint32_t Bhi = st + ST_BHI + b_base;
            const uint32_t Blo = st + ST_BLO + b_base;
#pragma unroll
            for (int ks = 0; ks < 2; ++ks) {
                const uint32_t ko = ks * 32u;
                uint32_t ah[2][4], aw[2][4], bh[14], bl[14];
                LDSM4(ah[0], Ahi + a_lane + ko);
                LDSM4(ah[1], Ahi + 1280u + a_lane + ko);
                LDSM4(&bh[0], Bhi + a_lane + ko);
                LDSM4(&bh[4], Bhi + 1280u + a_lane + ko);
                LDSM4(&bh[8], Bhi + 2560u + a_lane + ko);
                LDSM2(bh[12], bh[13], Bhi + 3840u + b2_lane + ko);
                PASS(ah, bh);                       // hi * hi
                LDSM4(&bl[0], Blo + a_lane + ko);
                LDSM4(&bl[4], Blo + 1280u + a_lane + ko);
                LDSM4(&bl[8], Blo + 2560u + a_lane + ko);
                LDSM2(bl[12], bl[13], Blo + 3840u + b2_lane + ko);
                PASS(ah, bl);                       // hi * lo
                LDSM4(aw[0], Alo + a_lane + ko);
                LDSM4(aw[1], Alo + 1280u + a_lane + ko);
                PASS(aw, bh);                       // lo * hi
            }
        }
        __syncthreads();
        if (c + 3 < NCH) issue_chunk(c + 3, s, tid, ybase, n0, brows, sm);
        s = (s == 2) ? 0 : s + 1;
    }

    // epilogue: write fp32 accumulators to g_map
    if (active) {
        const int mbase = blockIdx.x * 256 + wm * 32 + (lane >> 2);
        const int nlane = n0 + wn * 56 + (lane & 3) * 2;
#pragma unroll
        for (int i = 0; i < 2; ++i)
#pragma unroll
            for (int h = 0; h < 2; ++h) {
                const int p = mbase + i * 16 + h * 8;
                float* op = g_map + (size_t)p * CC;
#pragma unroll
                for (int j = 0; j < 7; ++j) {
                    int n = nlane + j * 8;
                    if (n < CC)
                        *(float2*)(op + n) = make_float2(acc[i][j][h * 2], acc[i][j][h * 2 + 1]);
                }
            }
    }
}

// ---------------------------------------------------------------------------
// Kernel: PS-RoI pool of conv map -> per-bin offsets (feature coords)
// ---------------------------------------------------------------------------
__global__ __launch_bounds__(256) void offset_pool_kernel(const float* __restrict__ rois, int N)
{
    int idx = blockIdx.x * blockDim.x + threadIdx.x;
    if (idx >= N * KK) return;
    int n   = idx / KK;
    int bin = idx - n * KK;
    int bi  = bin / KPOOL;
    int bj  = bin - bi * KPOOL;

    const float* r = rois + n * 5;
    float r1 = r[1], r2 = r[2], r3 = r[3], r4 = r[4];
    float x1 = r1 * 0.0625f;
    float y1 = r2 * 0.0625f;
    float x2 = (r3 + 1.0f) * 0.0625f;
    float y2 = (r4 + 1.0f) * 0.0625f;
    float bw = (x2 - x1) / 7.0f;
    float bh = (y2 - y1) / 7.0f;
    float cx = x1 + ((float)bj + 0.5f) * bw;
    float cy = y1 + ((float)bi + 0.5f) * bh;

    float y0f = floorf(cy), x0f = floorf(cx);
    float wy = cy - y0f,    wx = cx - x0f;
    int iy0 = min(max((int)y0f, 0), HH - 1);
    int iy1 = min(max((int)y0f + 1, 0), HH - 1);
    int ix0 = min(max((int)x0f, 0), WW - 1);
    int ix1 = min(max((int)x0f + 1, 0), WW - 1);

    float w00 = (1.f - wy) * (1.f - wx);
    float w01 = (1.f - wy) * wx;
    float w10 = wy * (1.f - wx);
    float w11 = wy * wx;

    const float* p00 = g_map + ((size_t)(iy0 * WW + ix0)) * CC + bin * 8;
    const float* p01 = g_map + ((size_t)(iy0 * WW + ix1)) * CC + bin * 8;
    const float* p10 = g_map + ((size_t)(iy1 * WW + ix0)) * CC + bin * 8;
    const float* p11 = g_map + ((size_t)(iy1 * WW + ix1)) * CC + bin * 8;

    float rw = r3 - r1 + 1.0f;
    float rh = r4 - r2 + 1.0f;

    float* o = g_off + (size_t)idx * 8;
#pragma unroll
    for (int g = 0; g < 4; ++g) {
        int d0 = g * 2, d1 = g * 2 + 1;
        float px = w00 * p00[d0] + w01 * p01[d0] + w10 * p10[d0] + w11 * p11[d0];
        float py = w00 * p00[d1] + w01 * p01[d1] + w10 * p10[d1] + w11 * p11[d1];
        o[d0] = (px * rw) * 0.1f * 0.0625f;
        o[d1] = (py * rh) * 0.1f * 0.0625f;
    }
}

// ---------------------------------------------------------------------------
// Kernel: deformable PS-RoI pool of raw features -> output [N,8,7,7]
// ---------------------------------------------------------------------------
__global__ __launch_bounds__(256) void deform_pool_kernel(const float* __restrict__ f,
                                                          const float* __restrict__ rois,
                                                          float* __restrict__ out, int N)
{
    int idx = blockIdx.x * blockDim.x + threadIdx.x;
    if (idx >= N * KK * 8) return;
    int d   = idx & 7;
    int nb  = idx >> 3;
    int n   = nb / KK;
    int bin = nb - n * KK;
    int bi  = bin / KPOOL;
    int bj  = bin - bi * KPOOL;

    const float* r = rois + n * 5;
    float x1 = r[1] * 0.0625f;
    float y1 = r[2] * 0.0625f;
    float x2 = (r[3] + 1.0f) * 0.0625f;
    float y2 = (r[4] + 1.0f) * 0.0625f;
    float bw = (x2 - x1) / 7.0f;
    float bh = (y2 - y1) / 7.0f;
    float cx = x1 + ((float)bj + 0.5f) * bw;
    float cy = y1 + ((float)bi + 0.5f) * bh;

    int g = d >> 1;
    const float* o = g_off + (size_t)nb * 8 + g * 2;
    float sx = cx + o[0];
    float sy = cy + o[1];

    float y0f = floorf(sy), x0f = floorf(sx);
    float wy = sy - y0f,    wx = sx - x0f;
    int iy0 = min(max((int)y0f, 0), HH - 1);
    int iy1 = min(max((int)y0f + 1, 0), HH - 1);
    int ix0 = min(max((int)x0f, 0), WW - 1);
    int ix1 = min(max((int)x0f + 1, 0), WW - 1);

    int ch = bin * 8 + d;
    float v00 = __ldg(f + ((size_t)(iy0 * WW + ix0)) * CC + ch);
    float v01 = __ldg(f + ((size_t)(iy0 * WW + ix1)) * CC + ch);
    float v10 = __ldg(f + ((size_t)(iy1 * WW + ix0)) * CC + ch);
    float v11 = __ldg(f + ((size_t)(iy1 * WW + ix1)) * CC + ch);

    float val = (1.f - wy) * (1.f - wx) * v00 + (1.f - wy) * wx * v01
              + wy * (1.f - wx) * v10 + wy * wx * v11;

    out[((size_t)n * 8 + d) * KK + bin] = val;
}

// ---------------------------------------------------------------------------
extern "C" void kernel_launch(void* const* d_in, const int* in_sizes, int n_in,
                              void* d_out, int out_size)
{
    const float* features = (const float*)d_in[0];  // [1,128,128,392]
    const float* rois     = (const float*)d_in[1];  // [N,5]
    const float* conv_w   = (const float*)d_in[2];  // [3,3,392,392]
    float* out = (float*)d_out;
    int N = in_sizes[1] / 5;

    cudaFuncSetAttribute(conv_mma_kernel, cudaFuncAttributeMaxDynamicSharedMemorySize, SMEM_BYTES);

    {
        int tot = PFW * PFW * (CPAD / 4);
        pad_split_features<<<(tot + 255) / 256, 256>>>(features);
        dim3 gw(13, 13, 9);
        split_weights<<<gw, 256>>>(conv_w);
        int pt = CC * 9 * (CPAD - CC);
        pad_weights_tail<<<(pt + 255) / 256, 256>>>();
    }

    {
        dim3 g(HH / 2, 4);   // 64 M-tiles (256 pixels) x {112,112,112,56} N-tiles
        conv_mma_kernel<<<g, 512, SMEM_BYTES>>>();
    }

    int t2 = N * KK;
    offset_pool_kernel<<<(t2 + 255) / 256, 256>>>(rois, N);

    int t3 = N * KK * 8;
    deform_pool_kernel<<<(t3 + 255) / 256, 256>>>(features, rois, out, N);
}

// round 9
// speedup vs baseline: 2.8014x; 1.2190x over previous
#include <cuda_runtime.h>
#include <cuda_bf16.h>
#include <cstdint>

#define HH 128
#define WW 128
#define CC 392
#define KPOOL 7
#define KK 49
#define MAXN 2048

#define CPAD 416              // channels padded (13 x 32)
#define PFW 130               // padded spatial (halo 1)
#define KTOT (9 * CPAD)       // 3744
#define NCH 117               // 9 taps * 13 ci-blocks of 32

#define NTILES 896            // 128 M-tiles (rows) x 7 N-tiles (56)
#define GRID 296              // 148 SMs x 2 CTAs

// smem per stage (bytes): A_hi[128*64] A_lo[128*64] B_hi[56*64] B_lo[56*64]
#define ST_AHI 0
#define ST_ALO 8192
#define ST_BHI 16384
#define ST_BLO 19968
#define STAGE_BYTES 23552
#define SMEM_BYTES (3 * STAGE_BYTES)

// ---------------------------------------------------------------------------
// Device scratch (no allocation allowed)
// ---------------------------------------------------------------------------
__device__ __nv_bfloat16 g_pf_hi[PFW * PFW * CPAD];
__device__ __nv_bfloat16 g_pf_lo[PFW * PFW * CPAD];
__device__ __nv_bfloat16 g_wt_hi[CC * KTOT];      // [n][k]
__device__ __nv_bfloat16 g_wt_lo[CC * KTOT];
__device__ float g_map[HH * WW * CC];
__device__ float g_off[MAXN * KK * 8];

// ---------------------------------------------------------------------------
// PTX helpers (baseline sm_80-era — safe for compute_103)
// ---------------------------------------------------------------------------
__device__ __forceinline__ uint32_t smem_u32(const void* p) {
    uint32_t a;
    asm("{ .reg .u64 t; cvta.to.shared.u64 t, %1; cvt.u32.u64 %0, t; }" : "=r"(a) : "l"(p));
    return a;
}
#define CP16(dst, src) \
    asm volatile("cp.async.cg.shared.global [%0], [%1], 16;" :: "r"(dst), "l"(src))
#define CP_COMMIT() asm volatile("cp.async.commit_group;" ::: "memory")
#define CP_WAIT2() asm volatile("cp.async.wait_group 2;" ::: "memory")
#define CP_WAIT1() asm volatile("cp.async.wait_group 1;" ::: "memory")
#define CP_WAIT0() asm volatile("cp.async.wait_group 0;" ::: "memory")

#define LDSM4(r, a) \
    asm volatile("ldmatrix.sync.aligned.m8n8.x4.shared.b16 {%0,%1,%2,%3}, [%4];" \
        : "=r"((r)[0]), "=r"((r)[1]), "=r"((r)[2]), "=r"((r)[3]) : "r"(a))
#define LDSM2(r0, r1, a) \
    asm volatile("ldmatrix.sync.aligned.m8n8.x2.shared.b16 {%0,%1}, [%2];" \
        : "=r"(r0), "=r"(r1) : "r"(a))

#define MMA(ar, b0, b1, cc) \
    asm volatile("mma.sync.aligned.m16n8k16.row.col.f32.bf16.bf16.f32 " \
        "{%0,%1,%2,%3}, {%4,%5,%6,%7}, {%8,%9}, {%0,%1,%2,%3};" \
        : "+f"((cc)[0]), "+f"((cc)[1]), "+f"((cc)[2]), "+f"((cc)[3]) \
        : "r"((ar)[0]), "r"((ar)[1]), "r"((ar)[2]), "r"((ar)[3]), "r"(b0), "r"(b1))

// one A frag (m16) x 7 n8 frags
#define PASS(A, B) do { \
    MMA((A), (B)[0], (B)[2],  acc[0]); MMA((A), (B)[1], (B)[3],  acc[1]); \
    MMA((A), (B)[4], (B)[6],  acc[2]); MMA((A), (B)[5], (B)[7],  acc[3]); \
    MMA((A), (B)[8], (B)[10], acc[4]); MMA((A), (B)[9], (B)[11], acc[5]); \
    MMA((A), (B)[12], (B)[13], acc[6]); \
} while (0)

// swizzled smem offset: 64B rows, seg = 16B column (0..3)
__device__ __forceinline__ uint32_t swz(int row, int seg) {
    return (uint32_t)(row * 64 + ((seg ^ ((row >> 1) & 3)) << 4));
}

// ---------------------------------------------------------------------------
// Precompute 1: pad + hi/lo split features -> g_pf_hi/lo [130,130,416]
// ---------------------------------------------------------------------------
__global__ __launch_bounds__(256) void pad_split_features(const float* __restrict__ f)
{
    int idx = blockIdx.x * 256 + threadIdx.x;
    const int TOT = PFW * PFW * (CPAD / 4);
    if (idx >= TOT) return;
    int p = idx / (CPAD / 4);
    int c0 = (idx - p * (CPAD / 4)) * 4;
    int y = p / PFW - 1;
    int x = p - (y + 1) * PFW - 1;
    bool in = ((unsigned)y < HH) && ((unsigned)x < WW);
    uint16_t h[4], l[4];
#pragma unroll
    for (int j = 0; j < 4; ++j) {
        int c = c0 + j;
        float v = (in && c < CC) ? __ldg(f + ((size_t)(y * WW + x)) * CC + c) : 0.f;
        __nv_bfloat16 hb = __float2bfloat16(v);
        float r = v - __bfloat162float(hb);
        __nv_bfloat16 lb = __float2bfloat16(r);
        h[j] = __bfloat16_as_ushort(hb);
        l[j] = __bfloat16_as_ushort(lb);
    }
    size_t o = (size_t)p * CPAD + c0;
    *(uint2*)(g_pf_hi + o) = make_uint2((uint32_t)h[0] | ((uint32_t)h[1] << 16),
                                        (uint32_t)h[2] | ((uint32_t)h[3] << 16));
    *(uint2*)(g_pf_lo + o) = make_uint2((uint32_t)l[0] | ((uint32_t)l[1] << 16),
                                        (uint32_t)l[2] | ((uint32_t)l[3] << 16));
}

// ---------------------------------------------------------------------------
// Precompute 2: coalesced transpose + split weights -> g_wt_hi/lo [392][3744]
// ---------------------------------------------------------------------------
__global__ __launch_bounds__(256) void split_weights(const float* __restrict__ w)
{
    __shared__ float tile[32][33];
    const int tap = blockIdx.z;
    const int ci0 = blockIdx.x * 32;
    const int n0  = blockIdx.y * 32;
    const int tx = threadIdx.x & 31;
    const int ty = threadIdx.x >> 5;
#pragma unroll
    for (int r = 0; r < 4; ++r) {
        int ci = ci0 + ty + r * 8;
        int n  = n0 + tx;
        float v = 0.f;
        if (ci < CC && n < CC) v = __ldg(w + ((size_t)(tap * CC + ci)) * CC + n);
        tile[ty + r * 8][tx] = v;
    }
    __syncthreads();
#pragma unroll
    for (int r = 0; r < 4; ++r) {
        int n  = n0 + ty + r * 8;
        int ci = ci0 + tx;
        if (n < CC && ci < CPAD) {
            float v = (ci < CC) ? tile[tx][ty + r * 8] : 0.f;
            __nv_bfloat16 hb = __float2bfloat16(v);
            float res = v - __bfloat162float(hb);
            size_t o = (size_t)n * KTOT + tap * CPAD + ci;
            g_wt_hi[o] = hb;
            g_wt_lo[o] = __float2bfloat16(res);
        }
    }
}

__global__ __launch_bounds__(256) void pad_weights_tail()
{
    int idx = blockIdx.x * 256 + threadIdx.x;
    const int TOT = CC * 9 * (CPAD - CC);
    if (idx >= TOT) return;
    int n = idx / (9 * (CPAD - CC));
    int rem = idx - n * 9 * (CPAD - CC);
    int tap = rem / (CPAD - CC);
    int ci = CC + rem - tap * (CPAD - CC);
    size_t o = (size_t)n * KTOT + tap * CPAD + ci;
    g_wt_hi[o] = __float2bfloat16(0.f);
    g_wt_lo[o] = __float2bfloat16(0.f);
}

// ---------------------------------------------------------------------------
// Conv implicit GEMM, persistent. Tile: BM=128 (1 row), BN=56. 256 threads,
// 8 warps on M (warp tile 16x56). 3-pass hi/lo, 3-stage cp.async, XOR swizzle.
// ---------------------------------------------------------------------------
__device__ __forceinline__ void issue_chunk(int c, int s, int tid, int y, int n0, uint32_t sm)
{
    int tap = c / 13;
    int ci0 = (c - tap * 13) * 32;
    int dy = tap / 3 - 1;
    int dx = tap - (tap / 3) * 3 - 1;
    uint32_t sbase = sm + s * STAGE_BYTES;
    // A: 128 rows x 64B x 2 mats = 1024 x 16B over 256 threads
#pragma unroll
    for (int t = 0; t < 4; ++t) {
        int i = tid + t * 256;
        int mat = i >> 9;
        int r = (i >> 2) & 127;
        int seg = i & 3;
        const __nv_bfloat16* g = mat ? g_pf_lo : g_pf_hi;
        const __nv_bfloat16* src = g
            + ((size_t)((y + dy + 1) * PFW + (r + dx + 1))) * CPAD + ci0 + seg * 8;
        uint32_t dst = sbase + mat * 8192 + swz(r, seg);
        CP16(dst, src);
    }
    // B: 56 rows x 64B x 2 mats = 448 x 16B
#pragma unroll
    for (int t = 0; t < 2; ++t) {
        int i = tid + t * 256;
        if (i < 448) {
            int mat = (i >= 224);
            int ii = i - mat * 224;
            int rr = ii >> 2;
            int seg = ii & 3;
            const __nv_bfloat16* g = mat ? g_wt_lo : g_wt_hi;
            const __nv_bfloat16* src = g + (size_t)(n0 + rr) * KTOT + tap * CPAD + ci0 + seg * 8;
            uint32_t dst = sbase + ST_BHI + mat * 3584 + swz(rr, seg);
            CP16(dst, src);
        }
    }
    CP_COMMIT();
}

__global__ void __launch_bounds__(256, 2) conv_mma_kernel()
{
    extern __shared__ char smem[];
    uint32_t sm = smem_u32(smem);
    const int tid  = threadIdx.x;
    const int lane = tid & 31;
    const int wid  = tid >> 5;

    const int l15 = lane & 15;
    const int l7  = lane & 7;
    const int hi16 = lane >> 4;          // 0/1: k-seg select for LDSM4
    const int hi8  = (lane >> 3) & 1;    // k-seg select for LDSM2
    const int arow = wid * 16 + l15;

#pragma unroll 1
    for (int tt = blockIdx.x; tt < NTILES; tt += GRID) {
        const int y  = tt / 7;
        const int n0 = (tt - y * 7) * 56;

        float acc[7][4];
#pragma unroll
        for (int j = 0; j < 7; ++j)
#pragma unroll
            for (int q = 0; q < 4; ++q) acc[j][q] = 0.f;

        issue_chunk(0, 0, tid, y, n0, sm);
        issue_chunk(1, 1, tid, y, n0, sm);
        issue_chunk(2, 2, tid, y, n0, sm);

        int s = 0;
#pragma unroll 1
        for (int c = 0; c < NCH; ++c) {
            if (c < NCH - 2)       { CP_WAIT2(); }
            else if (c == NCH - 2) { CP_WAIT1(); }
            else                   { CP_WAIT0(); }
            __syncthreads();
            const uint32_t st  = sm + s * STAGE_BYTES;
            const uint32_t Ahi = st + ST_AHI;
            const uint32_t Alo = st + ST_ALO;
            const uint32_t Bhi = st + ST_BHI;
            const uint32_t Blo = st + ST_BLO;
#pragma unroll
            for (int ks = 0; ks < 2; ++ks) {
                const int sa = ks * 2 + hi16;
                const int s2 = ks * 2 + hi8;
                uint32_t ah[4], aw[4], bh[14], bl[14];
                const uint32_t aoff = swz(arow, sa);
                LDSM4(ah, Ahi + aoff);
                LDSM4(&bh[0], Bhi + swz(l15, sa));
                LDSM4(&bh[4], Bhi + swz(16 + l15, sa));
                LDSM4(&bh[8], Bhi + swz(32 + l15, sa));
                LDSM2(bh[12], bh[13], Bhi + swz(48 + l7, s2));
                PASS(ah, bh);                       // hi * hi
                LDSM4(&bl[0], Blo + swz(l15, sa));
                LDSM4(&bl[4], Blo + swz(16 + l15, sa));
                LDSM4(&bl[8], Blo + swz(32 + l15, sa));
                LDSM2(bl[12], bl[13], Blo + swz(48 + l7, s2));
                PASS(ah, bl);                       // hi * lo
                LDSM4(aw, Alo + aoff);
                PASS(aw, bh);                       // lo * hi
            }
            __syncthreads();
            if (c + 3 < NCH) issue_chunk(c + 3, s, tid, y, n0, sm);
            s = (s == 2) ? 0 : s + 1;
        }

        // epilogue: warp tile 16x56 -> g_map[y, x, n]
        {
            const int nlane = n0 + (lane & 3) * 2;
#pragma unroll
            for (int h = 0; h < 2; ++h) {
                const int x = wid * 16 + (lane >> 2) + h * 8;
                float* op = g_map + ((size_t)(y * WW + x)) * CC;
#pragma unroll
                for (int j = 0; j < 7; ++j)
                    *(float2*)(op + nlane + j * 8) =
                        make_float2(acc[j][h * 2], acc[j][h * 2 + 1]);
            }
        }
    }
}

// ---------------------------------------------------------------------------
// Kernel: PS-RoI pool of conv map -> per-bin offsets (feature coords)
// ---------------------------------------------------------------------------
__global__ __launch_bounds__(256) void offset_pool_kernel(const float* __restrict__ rois, int N)
{
    int idx = blockIdx.x * blockDim.x + threadIdx.x;
    if (idx >= N * KK) return;
    int n   = idx / KK;
    int bin = idx - n * KK;
    int bi  = bin / KPOOL;
    int bj  = bin - bi * KPOOL;

    const float* r = rois + n * 5;
    float r1 = r[1], r2 = r[2], r3 = r[3], r4 = r[4];
    float x1 = r1 * 0.0625f;
    float y1 = r2 * 0.0625f;
    float x2 = (r3 + 1.0f) * 0.0625f;
    float y2 = (r4 + 1.0f) * 0.0625f;
    float bw = (x2 - x1) / 7.0f;
    float bh = (y2 - y1) / 7.0f;
    float cx = x1 + ((float)bj + 0.5f) * bw;
    float cy = y1 + ((float)bi + 0.5f) * bh;

    float y0f = floorf(cy), x0f = floorf(cx);
    float wy = cy - y0f,    wx = cx - x0f;
    int iy0 = min(max((int)y0f, 0), HH - 1);
    int iy1 = min(max((int)y0f + 1, 0), HH - 1);
    int ix0 = min(max((int)x0f, 0), WW - 1);
    int ix1 = min(max((int)x0f + 1, 0), WW - 1);

    float w00 = (1.f - wy) * (1.f - wx);
    float w01 = (1.f - wy) * wx;
    float w10 = wy * (1.f - wx);
    float w11 = wy * wx;

    const float* p00 = g_map + ((size_t)(iy0 * WW + ix0)) * CC + bin * 8;
    const float* p01 = g_map + ((size_t)(iy0 * WW + ix1)) * CC + bin * 8;
    const float* p10 = g_map + ((size_t)(iy1 * WW + ix0)) * CC + bin * 8;
    const float* p11 = g_map + ((size_t)(iy1 * WW + ix1)) * CC + bin * 8;

    float rw = r3 - r1 + 1.0f;
    float rh = r4 - r2 + 1.0f;

    float* o = g_off + (size_t)idx * 8;
#pragma unroll
    for (int g = 0; g < 4; ++g) {
        int d0 = g * 2, d1 = g * 2 + 1;
        float px = w00 * p00[d0] + w01 * p01[d0] + w10 * p10[d0] + w11 * p11[d0];
        float py = w00 * p00[d1] + w01 * p01[d1] + w10 * p10[d1] + w11 * p11[d1];
        o[d0] = (px * rw) * 0.1f * 0.0625f;
        o[d1] = (py * rh) * 0.1f * 0.0625f;
    }
}

// ---------------------------------------------------------------------------
// Kernel: deformable PS-RoI pool of raw features -> output [N,8,7,7]
// ---------------------------------------------------------------------------
__global__ __launch_bounds__(256) void deform_pool_kernel(const float* __restrict__ f,
                                                          const float* __restrict__ rois,
                                                          float* __restrict__ out, int N)
{
    int idx = blockIdx.x * blockDim.x + threadIdx.x;
    if (idx >= N * KK * 8) return;
    int d   = idx & 7;
    int nb  = idx >> 3;
    int n   = nb / KK;
    int bin = nb - n * KK;
    int bi  = bin / KPOOL;
    int bj  = bin - bi * KPOOL;

    const float* r = rois + n * 5;
    float x1 = r[1] * 0.0625f;
    float y1 = r[2] * 0.0625f;
    float x2 = (r[3] + 1.0f) * 0.0625f;
    float y2 = (r[4] + 1.0f) * 0.0625f;
    float bw = (x2 - x1) / 7.0f;
    float bh = (y2 - y1) / 7.0f;
    float cx = x1 + ((float)bj + 0.5f) * bw;
    float cy = y1 + ((float)bi + 0.5f) * bh;

    int g = d >> 1;
    const float* o = g_off + (size_t)nb * 8 + g * 2;
    float sx = cx + o[0];
    float sy = cy + o[1];

    float y0f = floorf(sy), x0f = floorf(sx);
    float wy = sy - y0f,    wx = sx - x0f;
    int iy0 = min(max((int)y0f, 0), HH - 1);
    int iy1 = min(max((int)y0f + 1, 0), HH - 1);
    int ix0 = min(max((int)x0f, 0), WW - 1);
    int ix1 = min(max((int)x0f + 1, 0), WW - 1);

    int ch = bin * 8 + d;
    float v00 = __ldg(f + ((size_t)(iy0 * WW + ix0)) * CC + ch);
    float v01 = __ldg(f + ((size_t)(iy0 * WW + ix1)) * CC + ch);
    float v10 = __ldg(f + ((size_t)(iy1 * WW + ix0)) * CC + ch);
    float v11 = __ldg(f + ((size_t)(iy1 * WW + ix1)) * CC + ch);

    float val = (1.f - wy) * (1.f - wx) * v00 + (1.f - wy) * wx * v01
              + wy * (1.f - wx) * v10 + wy * wx * v11;

    out[((size_t)n * 8 + d) * KK + bin] = val;
}

// ---------------------------------------------------------------------------
extern "C" void kernel_launch(void* const* d_in, const int* in_sizes, int n_in,
                              void* d_out, int out_size)
{
    const float* features = (const float*)d_in[0];  // [1,128,128,392]
    const float* rois     = (const float*)d_in[1];  // [N,5]
    const float* conv_w   = (const float*)d_in[2];  // [3,3,392,392]
    float* out = (float*)d_out;
    int N = in_sizes[1] / 5;

    cudaFuncSetAttribute(conv_mma_kernel, cudaFuncAttributeMaxDynamicSharedMemorySize, SMEM_BYTES);

    {
        int tot = PFW * PFW * (CPAD / 4);
        pad_split_features<<<(tot + 255) / 256, 256>>>(features);
        dim3 gw(13, 13, 9);
        split_weights<<<gw, 256>>>(conv_w);
        int pt = CC * 9 * (CPAD - CC);
        pad_weights_tail<<<(pt + 255) / 256, 256>>>();
    }

    conv_mma_kernel<<<GRID, 256, SMEM_BYTES>>>();

    int t2 = N * KK;
    offset_pool_kernel<<<(t2 + 255) / 256, 256>>>(rois, N);

    int t3 = N * KK * 8;
    deform_pool_kernel<<<(t3 + 255) / 256, 256>>>(features, rois, out, N);
}